// round 15
// baseline (speedup 1.0000x reference)
#include <cuda_runtime.h>

#define TLEN 65536
#define INPD 5
#define HD 100
#define HP 104            // padded h stride (16B-aligned)
#define G4 400            // 4*HD
#define THR 200           // fused kernel block size: 2 gate-rows per thread
#define CHUNK 4
#define NCHUNK (TLEN / CHUNK)
#define NCH8 (TLEN / 8)   // 8-step flag granularity
#define XG_TILE 16

// ---------------- static device scratch ----------------
// xg layout: [t][gate_row]  (coalesced across threads in the rec block)
__device__ float g_xg0[(size_t)TLEN * G4];
__device__ float g_xg1[(size_t)TLEN * G4];
__device__ float g_h1[(size_t)TLEN * HD];
__device__ float g_h2[(size_t)TLEN * HD];
__device__ int   g_prog0;           // layer-0 8-step chunks completed
__device__ int   g_ready[NCH8];     // xg1 8-step chunk ready flags

// ---------------- helpers ----------------
typedef unsigned long long u64;

__device__ __forceinline__ u64 ffma2(u64 a, u64 b, u64 c) {
    u64 d;
    asm("fma.rn.f32x2 %0, %1, %2, %3;" : "=l"(d) : "l"(a), "l"(b), "l"(c));
    return d;
}
#define ONE2 0x3F8000003F800000ull
__device__ __forceinline__ u64 fadd2(u64 a, u64 b) { return ffma2(a, ONE2, b); }
__device__ __forceinline__ float2 unpack2(u64 v) {
    float2 r;
    asm("mov.b64 {%0, %1}, %2;" : "=f"(r.x), "=f"(r.y) : "l"(v));
    return r;
}
__device__ __forceinline__ u64 pack2(float lo, float hi) {
    u64 v;
    asm("mov.b64 %0, {%1, %2};" : "=l"(v) : "f"(lo), "f"(hi));
    return v;
}
__device__ __forceinline__ float tanh_ap(float x) {
    float y;
    asm("tanh.approx.f32 %0, %1;" : "=f"(y) : "f"(x));
    return y;
}
__device__ __forceinline__ float sigmoid_ap(float x) {
    return __fmaf_rn(0.5f, tanh_ap(0.5f * x), 0.5f);
}
__device__ __forceinline__ int ld_acq(const int* p) {
    int v;
    asm volatile("ld.acquire.gpu.global.b32 %0, [%1];" : "=r"(v) : "l"(p) : "memory");
    return v;
}
__device__ __forceinline__ void sts_pred(int pred, unsigned addr, float v) {
    asm volatile("{ .reg .pred p; setp.ne.s32 p, %0, 0; @p st.shared.f32 [%1], %2; }"
                 :: "r"(pred), "r"(addr), "f"(v));
}
__device__ __forceinline__ void stg_pred(int pred, float* addr, float v) {
    asm volatile("{ .reg .pred p; setp.ne.s32 p, %0, 0; @p st.global.cs.f32 [%1], %2; }"
                 :: "r"(pred), "l"(addr), "f"(v));
}

// two 100-dots sharing one set of h loads; w[0..49] row A, w[50..99] row B
__device__ __forceinline__ void dot2(const u64* __restrict__ w,
                                     const float* __restrict__ hvec,
                                     float i0, float i1, float& d0, float& d1) {
    const ulonglong2* hp = (const ulonglong2*)hvec;
    u64 a0 = pack2(i0, 0.f), a1 = 0ull;
    u64 b0 = pack2(i1, 0.f), b1 = 0ull;
#pragma unroll
    for (int k = 0; k < HD / 4; k++) {
        ulonglong2 hv = hp[k];
        a0 = ffma2(w[2 * k], hv.x, a0);
        a1 = ffma2(w[2 * k + 1], hv.y, a1);
        b0 = ffma2(w[50 + 2 * k], hv.x, b0);
        b1 = ffma2(w[50 + 2 * k + 1], hv.y, b1);
    }
    a0 = fadd2(a0, a1);
    b0 = fadd2(b0, b1);
    float2 s = unpack2(a0);
    float2 r = unpack2(b0);
    d0 = s.x + s.y;
    d1 = r.x + r.y;
}

__device__ __forceinline__ void load_wrow(u64* w, const float* row) {
    const ulonglong2* wr = (const ulonglong2*)row;
#pragma unroll
    for (int k = 0; k < HD / 4; k++) {
        ulonglong2 v = wr[k];
        w[2 * k] = v.x;
        w[2 * k + 1] = v.y;
    }
}

// ---------------- phase 1: xg0 = Wih0 @ x[t] + bih0 + bhh0 (+ flag reset) ------
__global__ void xg0_kernel(const float* __restrict__ x,
                           const float* __restrict__ Wih0,
                           const float* __restrict__ bih0,
                           const float* __restrict__ bhh0) {
    int g = threadIdx.x;                 // 0..399
    if (blockIdx.x == 0) {               // reset cross-block flags for this run
        for (int i = g; i < NCH8; i += G4) g_ready[i] = 0;
        if (g == 0) g_prog0 = 0;
    }
    int t0 = blockIdx.x * XG_TILE;
    float w0 = __ldg(Wih0 + g * INPD + 0);
    float w1 = __ldg(Wih0 + g * INPD + 1);
    float w2 = __ldg(Wih0 + g * INPD + 2);
    float w3 = __ldg(Wih0 + g * INPD + 3);
    float w4 = __ldg(Wih0 + g * INPD + 4);
    float b = __ldg(bih0 + g) + __ldg(bhh0 + g);
#pragma unroll
    for (int tt = 0; tt < XG_TILE; tt++) {
        const float* xr = x + (size_t)(t0 + tt) * INPD;
        float acc = b;
        acc = __fmaf_rn(w0, __ldg(xr + 0), acc);
        acc = __fmaf_rn(w1, __ldg(xr + 1), acc);
        acc = __fmaf_rn(w2, __ldg(xr + 2), acc);
        acc = __fmaf_rn(w3, __ldg(xr + 3), acc);
        acc = __fmaf_rn(w4, __ldg(xr + 4), acc);
        g_xg0[(size_t)(t0 + tt) * G4 + g] = acc;
    }
}

// ---------------- the 4-step chunk body (shared by ping/pong) ----------------
struct RecCtx {
    const u64* w;
    float* h_s;
    unsigned wrA, wrB;
    int p, isp0;
    float sc0, off0;
    unsigned mask;
};

__device__ __forceinline__ void rec_steps(const RecCtx& cx,
                                          const float* xc0, const float* xc1,
                                          float& c, float* hgp) {
#pragma unroll
    for (int s = 0; s < CHUNK; s++) {
        float d0, d1;
        dot2(cx.w, cx.h_s + (s & 1) * HP, xc0[s], xc1[s], d0, d1);
        float act0 = __fmaf_rn(cx.sc0, tanh_ap(cx.sc0 * d0), cx.off0);
        float act1 = sigmoid_ap(d1);
        float o0 = __shfl_xor_sync(cx.mask, act0, 1);
        float o1 = __shfl_xor_sync(cx.mask, act1, 1);
        // p0: i=act0 f=act1 g=o0 o=o1 ; p1: i=o0 f=o1 g=act0 o=act1
        float iv = cx.p ? o0 : act0;
        float fv = cx.p ? o1 : act1;
        float gg = cx.p ? act0 : o0;
        float ov = cx.p ? act1 : o1;
        c = __fmaf_rn(fv, c, iv * gg);               // identical on both lanes
        float h = ov * tanh_ap(c);
        sts_pred(cx.isp0, (s & 1) ? cx.wrB : cx.wrA, h);
        stg_pred(cx.isp0, hgp + (size_t)s * HD, h);
        __syncthreads();
    }
}

// ---------------- recurrence body (one block, 200 threads) ----------------
// tid = 2*j + p : unit j (0..99); p=0 owns rows {i_j, f_j}, p=1 owns {g_j, o_j}
// Ping-pong chunk buffers (xrA/xrB): no per-chunk register copies.
template <bool RELEASE, bool WAIT>
__device__ void rec_body(const float* __restrict__ Whh,
                         const float* __restrict__ xg,
                         float* __restrict__ hout,
                         float* __restrict__ h_s /* [2][HP] smem */) {
    int tid = threadIdx.x;
    int j = tid >> 1, p = tid & 1;
    int row0 = p * 2 * HD + j;

    RecCtx cx;
    cx.h_s = h_s;
    cx.p = p;
    cx.isp0 = (p == 0);
    cx.mask = 0xffffffffu;
    cx.sc0  = p ? 1.0f : 0.5f;           // row0: p0 sigmoid(i), p1 tanh(g)
    cx.off0 = p ? 0.0f : 0.5f;

    u64 w[100];
    load_wrow(w,      Whh + (size_t)row0 * HD);
    load_wrow(w + 50, Whh + (size_t)(row0 + HD) * HD);
    cx.w = w;

    cx.wrA = (unsigned)__cvta_generic_to_shared(h_s + HP + j);  // even s writes
    cx.wrB = (unsigned)__cvta_generic_to_shared(h_s + j);       // odd s writes
    float* hgp = hout + j;
    const float* xp = xg + row0;         // second row at +HD (immediate offset)

    for (int i = tid; i < 2 * HP; i += THR) h_s[i] = 0.f;
    float c = 0.f;

    if (WAIT) {
        while (ld_acq(&g_ready[0]) == 0) __nanosleep(40);
    }
    float xrA0[CHUNK], xrA1[CHUNK], xrB0[CHUNK], xrB1[CHUNK];
#pragma unroll
    for (int s = 0; s < CHUNK; s++) {    // chunk 0 -> A
        xrA0[s] = __ldcg(xp + (size_t)s * G4);
        xrA1[s] = __ldcg(xp + (size_t)s * G4 + HD);
    }
    const float* xq = xp + (size_t)CHUNK * G4;   // next chunk to prefetch
    int rdy = 1;                          // chunk 1 consumes flag[0], confirmed
    __syncthreads();

#pragma unroll 1
    for (int c0 = 0; c0 < NCHUNK; c0 += 2) {
        // ---- body A: chunk c0 (even), consumes A, prefetches c0+1 into B ----
        {
            if (WAIT && !rdy) {          // rare: probe (issued a chunk ago) said no
                while (ld_acq(&g_ready[(c0 + 1) >> 1]) == 0) __nanosleep(40);
            }
#pragma unroll
            for (int s = 0; s < CHUNK; s++) {         // c0+1 always < NCHUNK here
                xrB0[s] = __ldcg(xq + (size_t)s * G4);
                xrB1[s] = __ldcg(xq + (size_t)s * G4 + HD);
            }
            xq += (size_t)CHUNK * G4;
            if (WAIT && c0 + 2 < NCHUNK)
                rdy = ld_acq(&g_ready[(c0 + 2) >> 1]);

            rec_steps(cx, xrA0, xrA1, c, hgp);
            hgp += CHUNK * HD;
        }
        // ---- body B: chunk c0+1 (odd), consumes B, prefetches c0+2 into A ----
        {
            if (c0 + 2 < NCHUNK) {
                if (WAIT && !rdy) {
                    while (ld_acq(&g_ready[(c0 + 2) >> 1]) == 0) __nanosleep(40);
                }
#pragma unroll
                for (int s = 0; s < CHUNK; s++) {
                    xrA0[s] = __ldcg(xq + (size_t)s * G4);
                    xrA1[s] = __ldcg(xq + (size_t)s * G4 + HD);
                }
                xq += (size_t)CHUNK * G4;
                if (WAIT && c0 + 3 < NCHUNK)
                    rdy = ld_acq(&g_ready[(c0 + 3) >> 1]);
            }

            rec_steps(cx, xrB0, xrB1, c, hgp);
            hgp += CHUNK * HD;

            if (RELEASE && tid == 0) {   // end of odd chunk = every 8 steps
                __threadfence();
                *((volatile int*)&g_prog0) = (c0 + 2) >> 1;
            }
        }
    }
}

// ---------------- xg1 streaming body (2 blocks, alternate 8-step chunks) ------
// thread tid handles rows tid and tid+200
__device__ void xg_body(const float* __restrict__ Wih1,
                        const float* __restrict__ bih1,
                        const float* __restrict__ bhh1, int b,
                        float* __restrict__ hbuf /* [8][HP] smem */) {
    int tid = threadIdx.x;

    u64 w[100];
    load_wrow(w,      Wih1 + (size_t)tid * HD);
    load_wrow(w + 50, Wih1 + (size_t)(tid + 200) * HD);
    float bb0 = __ldg(bih1 + tid) + __ldg(bhh1 + tid);
    float bb1 = __ldg(bih1 + tid + 200) + __ldg(bhh1 + tid + 200);

    if (tid < 8 * 4) {                   // zero pad slots once
        int s = tid >> 2, q = tid & 3;
        hbuf[s * HP + HD + q] = 0.f;
    }

#pragma unroll 1
    for (int c0 = b; c0 < NCH8; c0 += 2) {
        while (ld_acq(&g_prog0) < c0 + 1) __nanosleep(64);
        __syncthreads();                 // protect hbuf reuse
        for (int i = tid; i < 8 * HD; i += THR)
            hbuf[(i / HD) * HP + (i % HD)] = __ldcg(g_h1 + (size_t)c0 * 8 * HD + i);
        __syncthreads();

#pragma unroll
        for (int s = 0; s < 8; s++) {
            float d0, d1;
            dot2(w, hbuf + s * HP, bb0, bb1, d0, d1);
            float* op = g_xg1 + (size_t)(c0 * 8 + s) * G4 + tid;
            __stcg(op, d0);
            __stcg(op + 200, d1);
        }
        __threadfence();
        __syncthreads();
        if (tid == 0)
            *((volatile int*)&g_ready[c0]) = 1;
    }
}

// ---------------- fused pipelined kernel: grid = 4 blocks ----------------
__global__ __launch_bounds__(THR, 1)
void fused_kernel(const float* __restrict__ Whh0,
                  const float* __restrict__ Whh1,
                  const float* __restrict__ Wih1,
                  const float* __restrict__ bih1,
                  const float* __restrict__ bhh1) {
    __shared__ __align__(16) float smem_pool[8 * HP];      // 3328 B
    int b = blockIdx.x;
    if (b == 0)
        rec_body<true, false>(Whh0, g_xg0, g_h1, smem_pool);
    else if (b <= 2)
        xg_body(Wih1, bih1, bhh1, b - 1, smem_pool);
    else
        rec_body<false, true>(Whh1, g_xg1, g_h2, smem_pool);
}

// ---------------- final linear + sigmoid ----------------
__global__ void out_kernel(const float* __restrict__ Wlin,
                           const float* __restrict__ blin,
                           float* __restrict__ out) {
    int warp = (blockIdx.x * blockDim.x + threadIdx.x) >> 5;
    int lane = threadIdx.x & 31;
    if (warp >= TLEN) return;
    const float* hr = g_h2 + (size_t)warp * HD;
    float acc = 0.f;
#pragma unroll
    for (int k = 0; k < 4; k++) {
        int idx = lane + 32 * k;
        if (idx < HD) acc = __fmaf_rn(hr[idx], __ldg(Wlin + idx), acc);
    }
#pragma unroll
    for (int o = 16; o; o >>= 1) acc += __shfl_down_sync(0xffffffffu, acc, o);
    if (lane == 0) out[warp] = sigmoid_ap(acc + __ldg(blin));
}

// ---------------- launch ----------------
extern "C" void kernel_launch(void* const* d_in, const int* in_sizes, int n_in,
                              void* d_out, int out_size) {
    const float* x    = (const float*)d_in[0];
    const float* Wih0 = (const float*)d_in[1];
    const float* Whh0 = (const float*)d_in[2];
    const float* bih0 = (const float*)d_in[3];
    const float* bhh0 = (const float*)d_in[4];
    const float* Wih1 = (const float*)d_in[5];
    const float* Whh1 = (const float*)d_in[6];
    const float* bih1 = (const float*)d_in[7];
    const float* bhh1 = (const float*)d_in[8];
    const float* Wlin = (const float*)d_in[9];
    const float* blin = (const float*)d_in[10];
    float* out = (float*)d_out;

    xg0_kernel<<<TLEN / XG_TILE, G4>>>(x, Wih0, bih0, bhh0);
    fused_kernel<<<4, THR>>>(Whh0, Whh1, Wih1, bih1, bhh1);
    out_kernel<<<(TLEN * 32) / 256, 256>>>(Wlin, blin, out);
}

// round 16
// speedup vs baseline: 1.0088x; 1.0088x over previous
#include <cuda_runtime.h>

#define TLEN 65536
#define INPD 5
#define HD 100
#define HP 104            // padded h stride (16B-aligned)
#define G4 400            // 4*HD
#define THR 200           // fused kernel block size: 2 gate-rows per thread
#define CHUNK 4
#define NCHUNK (TLEN / CHUNK)
#define NCH8 (TLEN / 8)   // 8-step flag granularity
#define XG_TILE 16

// ---------------- static device scratch ----------------
// xg layout: [t][gate_row]  (coalesced across threads in the rec block)
__device__ float g_xg0[(size_t)TLEN * G4];
__device__ float g_xg1[(size_t)TLEN * G4];
__device__ float g_h1[(size_t)TLEN * HD];
__device__ float g_h2[(size_t)TLEN * HD];
__device__ int   g_prog0;           // layer-0 8-step chunks completed
__device__ int   g_ready[NCH8];     // xg1 8-step chunk ready flags

// ---------------- helpers ----------------
typedef unsigned long long u64;

__device__ __forceinline__ u64 ffma2(u64 a, u64 b, u64 c) {
    u64 d;
    asm("fma.rn.f32x2 %0, %1, %2, %3;" : "=l"(d) : "l"(a), "l"(b), "l"(c));
    return d;
}
#define ONE2 0x3F8000003F800000ull
__device__ __forceinline__ u64 fadd2(u64 a, u64 b) { return ffma2(a, ONE2, b); }
__device__ __forceinline__ float2 unpack2(u64 v) {
    float2 r;
    asm("mov.b64 {%0, %1}, %2;" : "=f"(r.x), "=f"(r.y) : "l"(v));
    return r;
}
__device__ __forceinline__ u64 pack2(float lo, float hi) {
    u64 v;
    asm("mov.b64 %0, {%1, %2};" : "=l"(v) : "f"(lo), "f"(hi));
    return v;
}
__device__ __forceinline__ float tanh_ap(float x) {
    float y;
    asm("tanh.approx.f32 %0, %1;" : "=f"(y) : "f"(x));
    return y;
}
__device__ __forceinline__ float sigmoid_ap(float x) {
    return __fmaf_rn(0.5f, tanh_ap(0.5f * x), 0.5f);
}
__device__ __forceinline__ int ld_acq(const int* p) {
    int v;
    asm volatile("ld.acquire.gpu.global.b32 %0, [%1];" : "=r"(v) : "l"(p) : "memory");
    return v;
}
__device__ __forceinline__ void sts_pred(int pred, unsigned addr, float v) {
    asm volatile("{ .reg .pred p; setp.ne.s32 p, %0, 0; @p st.shared.f32 [%1], %2; }"
                 :: "r"(pred), "r"(addr), "f"(v));
}
__device__ __forceinline__ void stg_pred(int pred, float* addr, float v) {
    asm volatile("{ .reg .pred p; setp.ne.s32 p, %0, 0; @p st.global.cs.f32 [%1], %2; }"
                 :: "r"(pred), "l"(addr), "f"(v));
}

// two 100-dots sharing one set of h loads; w[0..49] row A, w[50..99] row B
__device__ __forceinline__ void dot2(const u64* __restrict__ w,
                                     const float* __restrict__ hvec,
                                     float i0, float i1, float& d0, float& d1) {
    const ulonglong2* hp = (const ulonglong2*)hvec;
    u64 a0 = pack2(i0, 0.f), a1 = 0ull;
    u64 b0 = pack2(i1, 0.f), b1 = 0ull;
#pragma unroll
    for (int k = 0; k < HD / 4; k++) {
        ulonglong2 hv = hp[k];
        a0 = ffma2(w[2 * k], hv.x, a0);
        a1 = ffma2(w[2 * k + 1], hv.y, a1);
        b0 = ffma2(w[50 + 2 * k], hv.x, b0);
        b1 = ffma2(w[50 + 2 * k + 1], hv.y, b1);
    }
    a0 = fadd2(a0, a1);
    b0 = fadd2(b0, b1);
    float2 s = unpack2(a0);
    float2 r = unpack2(b0);
    d0 = s.x + s.y;
    d1 = r.x + r.y;
}

__device__ __forceinline__ void load_wrow(u64* w, const float* row) {
    const ulonglong2* wr = (const ulonglong2*)row;
#pragma unroll
    for (int k = 0; k < HD / 4; k++) {
        ulonglong2 v = wr[k];
        w[2 * k] = v.x;
        w[2 * k + 1] = v.y;
    }
}

// ---------------- phase 1: xg0 = Wih0 @ x[t] + bih0 + bhh0 (+ flag reset) ------
__global__ void xg0_kernel(const float* __restrict__ x,
                           const float* __restrict__ Wih0,
                           const float* __restrict__ bih0,
                           const float* __restrict__ bhh0) {
    int g = threadIdx.x;                 // 0..399
    if (blockIdx.x == 0) {               // reset cross-block flags for this run
        for (int i = g; i < NCH8; i += G4) g_ready[i] = 0;
        if (g == 0) g_prog0 = 0;
    }
    int t0 = blockIdx.x * XG_TILE;
    float w0 = __ldg(Wih0 + g * INPD + 0);
    float w1 = __ldg(Wih0 + g * INPD + 1);
    float w2 = __ldg(Wih0 + g * INPD + 2);
    float w3 = __ldg(Wih0 + g * INPD + 3);
    float w4 = __ldg(Wih0 + g * INPD + 4);
    float b = __ldg(bih0 + g) + __ldg(bhh0 + g);
#pragma unroll
    for (int tt = 0; tt < XG_TILE; tt++) {
        const float* xr = x + (size_t)(t0 + tt) * INPD;
        float acc = b;
        acc = __fmaf_rn(w0, __ldg(xr + 0), acc);
        acc = __fmaf_rn(w1, __ldg(xr + 1), acc);
        acc = __fmaf_rn(w2, __ldg(xr + 2), acc);
        acc = __fmaf_rn(w3, __ldg(xr + 3), acc);
        acc = __fmaf_rn(w4, __ldg(xr + 4), acc);
        g_xg0[(size_t)(t0 + tt) * G4 + g] = acc;
    }
}

// ---------------- recurrence body (one block, 200 threads) ----------------
// tid = 2*j + p : unit j (0..99); p=0 owns rows {i_j, f_j}, p=1 owns {g_j, o_j}
// row0 = p*2*HD + j, row1 = row0 + HD. Both dots share h loads.
template <bool RELEASE, bool WAIT>
__device__ void rec_body(const float* __restrict__ Whh,
                         const float* __restrict__ xg,
                         float* __restrict__ hout,
                         float* __restrict__ h_s /* [2][HP] smem */) {
    int tid = threadIdx.x;
    int j = tid >> 1, p = tid & 1;
    int row0 = p * 2 * HD + j;
    int isp0 = (p == 0);
    unsigned mask = 0xffffffffu;

    // row0 activation: p0 -> sigmoid(i), p1 -> tanh(g). row1 always sigmoid (f / o).
    float sc0  = p ? 1.0f : 0.5f;
    float off0 = p ? 0.0f : 0.5f;

    u64 w[100];
    load_wrow(w,      Whh + (size_t)row0 * HD);
    load_wrow(w + 50, Whh + (size_t)(row0 + HD) * HD);

    unsigned wrA = (unsigned)__cvta_generic_to_shared(h_s + HP + j);  // even s writes
    unsigned wrB = (unsigned)__cvta_generic_to_shared(h_s + j);       // odd s writes
    float* hg = hout + j;
    const float* xp = xg + row0;         // second row at +HD (immediate offset)

    for (int i = tid; i < 2 * HP; i += THR) h_s[i] = 0.f;
    float c = 0.f;

    if (WAIT) {
        while (ld_acq(&g_ready[0]) == 0) __nanosleep(40);
    }
    float xr0[CHUNK], xr1[CHUNK];
#pragma unroll
    for (int s = 0; s < CHUNK; s++) {
        xr0[s] = __ldcg(xp + (size_t)s * G4);
        xr1[s] = __ldcg(xp + (size_t)s * G4 + HD);
    }
    int rdy = 1;                          // chunk 1 consumes flag[0], already confirmed
    __syncthreads();

#pragma unroll 1
    for (int c0 = 0; c0 < NCHUNK; c0++) {
        float xc0[CHUNK], xc1[CHUNK];
#pragma unroll
        for (int s = 0; s < CHUNK; s++) { xc0[s] = xr0[s]; xc1[s] = xr1[s]; }

        if (c0 + 1 < NCHUNK) {           // prefetch next chunk, off critical path
            if (WAIT && !rdy) {          // rare: probe (issued a full chunk ago) said no
                while (ld_acq(&g_ready[(c0 + 1) >> 1]) == 0) __nanosleep(40);
            }
            const float* xq = xg + (size_t)(c0 + 1) * CHUNK * G4 + row0;
#pragma unroll
            for (int s = 0; s < CHUNK; s++) {
                xr0[s] = __ldcg(xq + (size_t)s * G4);
                xr1[s] = __ldcg(xq + (size_t)s * G4 + HD);
            }
            if (WAIT && c0 + 2 < NCHUNK) // early probe for NEXT chunk's flag;
                rdy = ld_acq(&g_ready[(c0 + 2) >> 1]);  // consumed ~2000 cyc later
        }

#pragma unroll
        for (int s = 0; s < CHUNK; s++) {
            float d0, d1;
            dot2(w, h_s + (s & 1) * HP, xc0[s], xc1[s], d0, d1);
            float act0 = __fmaf_rn(sc0, tanh_ap(sc0 * d0), off0);
            float act1 = sigmoid_ap(d1);
            float o0 = __shfl_xor_sync(mask, act0, 1);
            float o1 = __shfl_xor_sync(mask, act1, 1);
            // p0: i=act0 f=act1 g=o0 o=o1 ; p1: i=o0 f=o1 g=act0 o=act1
            float iv = p ? o0 : act0;
            float fv = p ? o1 : act1;
            float gg = p ? act0 : o0;
            float ov = p ? act1 : o1;
            c = __fmaf_rn(fv, c, iv * gg);            // identical on both lanes
            float h = ov * tanh_ap(c);
            sts_pred(isp0, (s & 1) ? wrB : wrA, h);
            stg_pred(isp0, hg + (size_t)(c0 * CHUNK + s) * HD, h);
            __syncthreads();
        }

        if (RELEASE && (c0 & 1) && tid == 0) {        // every 8 steps
            __threadfence();
            *((volatile int*)&g_prog0) = (c0 + 1) >> 1;
        }
    }
}

// ---------------- xg1 streaming body (2 blocks, alternate 8-step chunks) ------
// thread tid handles rows tid and tid+200
__device__ void xg_body(const float* __restrict__ Wih1,
                        const float* __restrict__ bih1,
                        const float* __restrict__ bhh1, int b,
                        float* __restrict__ hbuf /* [8][HP] smem */) {
    int tid = threadIdx.x;

    u64 w[100];
    load_wrow(w,      Wih1 + (size_t)tid * HD);
    load_wrow(w + 50, Wih1 + (size_t)(tid + 200) * HD);
    float bb0 = __ldg(bih1 + tid) + __ldg(bhh1 + tid);
    float bb1 = __ldg(bih1 + tid + 200) + __ldg(bhh1 + tid + 200);

    if (tid < 8 * 4) {                   // zero pad slots once
        int s = tid >> 2, q = tid & 3;
        hbuf[s * HP + HD + q] = 0.f;
    }

#pragma unroll 1
    for (int c0 = b; c0 < NCH8; c0 += 2) {
        while (ld_acq(&g_prog0) < c0 + 1) __nanosleep(64);
        __syncthreads();                 // protect hbuf reuse
        for (int i = tid; i < 8 * HD; i += THR)
            hbuf[(i / HD) * HP + (i % HD)] = __ldcg(g_h1 + (size_t)c0 * 8 * HD + i);
        __syncthreads();

#pragma unroll
        for (int s = 0; s < 8; s++) {
            float d0, d1;
            dot2(w, hbuf + s * HP, bb0, bb1, d0, d1);
            float* op = g_xg1 + (size_t)(c0 * 8 + s) * G4 + tid;
            __stcg(op, d0);
            __stcg(op + 200, d1);
        }
        __threadfence();
        __syncthreads();
        if (tid == 0)
            *((volatile int*)&g_ready[c0]) = 1;
    }
}

// ---------------- fused pipelined kernel: grid = 4 blocks ----------------
__global__ __launch_bounds__(THR, 1)
void fused_kernel(const float* __restrict__ Whh0,
                  const float* __restrict__ Whh1,
                  const float* __restrict__ Wih1,
                  const float* __restrict__ bih1,
                  const float* __restrict__ bhh1) {
    __shared__ __align__(16) float smem_pool[8 * HP];      // 3328 B
    int b = blockIdx.x;
    if (b == 0)
        rec_body<true, false>(Whh0, g_xg0, g_h1, smem_pool);
    else if (b <= 2)
        xg_body(Wih1, bih1, bhh1, b - 1, smem_pool);
    else
        rec_body<false, true>(Whh1, g_xg1, g_h2, smem_pool);
}

// ---------------- final linear + sigmoid ----------------
__global__ void out_kernel(const float* __restrict__ Wlin,
                           const float* __restrict__ blin,
                           float* __restrict__ out) {
    int warp = (blockIdx.x * blockDim.x + threadIdx.x) >> 5;
    int lane = threadIdx.x & 31;
    if (warp >= TLEN) return;
    const float* hr = g_h2 + (size_t)warp * HD;
    float acc = 0.f;
#pragma unroll
    for (int k = 0; k < 4; k++) {
        int idx = lane + 32 * k;
        if (idx < HD) acc = __fmaf_rn(hr[idx], __ldg(Wlin + idx), acc);
    }
#pragma unroll
    for (int o = 16; o; o >>= 1) acc += __shfl_down_sync(0xffffffffu, acc, o);
    if (lane == 0) out[warp] = sigmoid_ap(acc + __ldg(blin));
}

// ---------------- launch ----------------
extern "C" void kernel_launch(void* const* d_in, const int* in_sizes, int n_in,
                              void* d_out, int out_size) {
    const float* x    = (const float*)d_in[0];
    const float* Wih0 = (const float*)d_in[1];
    const float* Whh0 = (const float*)d_in[2];
    const float* bih0 = (const float*)d_in[3];
    const float* bhh0 = (const float*)d_in[4];
    const float* Wih1 = (const float*)d_in[5];
    const float* Whh1 = (const float*)d_in[6];
    const float* bih1 = (const float*)d_in[7];
    const float* bhh1 = (const float*)d_in[8];
    const float* Wlin = (const float*)d_in[9];
    const float* blin = (const float*)d_in[10];
    float* out = (float*)d_out;

    xg0_kernel<<<TLEN / XG_TILE, G4>>>(x, Wih0, bih0, bhh0);
    fused_kernel<<<4, THR>>>(Whh0, Whh1, Wih1, bih1, bhh1);
    out_kernel<<<(TLEN * 32) / 256, 256>>>(Wlin, blin, out);
}